// round 15
// baseline (speedup 1.0000x reference)
#include <cuda_runtime.h>
#include <math.h>

#define N_TOT 65536      // B(64) * C(1024) columns
#define S_DIM 576
#define H_DIM 72
#define NT 11            // Taylor terms t = 0..10 of exp(2 xm_c xm_d)

// ---------------- scratch (device globals; no allocation allowed) ----------
__device__ float g_H1[H_DIM * N_TOT];          // 18.9 MB
__device__ float g_H2[H_DIM * N_TOT];          // 18.9 MB
__device__ float g_xm[N_TOT];
__device__ float g_R[128 * 73 * 12];           // per-group R_t (row 72 = m_t)
__device__ float g_Gpart[64 * H_DIM * H_DIM];  // per-block SYRK partials
__device__ float g_hpart[64 * H_DIM];
__device__ float g_G[H_DIM * H_DIM];
__device__ float g_hsum[H_DIM];
__device__ float g_M[H_DIM * H_DIM];
__device__ float g_yb[H_DIM];
__device__ float g_w2m[H_DIM];
__device__ float g_b2m;
__device__ float g_scale[S_DIM];
__device__ float g_shift[S_DIM];

// ---------------- K0: merged prep (74 blocks)  [verbatim] ------------------
__global__ void __launch_bounds__(128) k0_prep(const float* __restrict__ W2,
                                               const float* __restrict__ b2,
                                               const float* __restrict__ W3)
{
    __shared__ float row[S_DIM];
    int o = blockIdx.x;
    if (o < H_DIM) {
        for (int e = threadIdx.x; e < S_DIM; e += 128) row[e] = W3[o * S_DIM + e];
        __syncthreads();
        if (threadIdx.x < H_DIM) {
            int j = threadIdx.x;
            float a = 0.f;
            for (int s = 0; s < S_DIM; s++) a = fmaf(row[s], W2[s * H_DIM + j], a);
            g_M[o * H_DIM + j] = a;
        }
    } else if (o == H_DIM) {
        for (int e = threadIdx.x; e < S_DIM; e += 128) row[e] = b2[e];
        __syncthreads();
        if (threadIdx.x < H_DIM) {
            int oo = threadIdx.x;
            float a = 0.f;
            for (int s = 0; s < S_DIM; s++) a = fmaf(W3[oo * S_DIM + s], row[s], a);
            g_yb[oo] = a;
        }
    } else {
        if (threadIdx.x < H_DIM) {
            int j = threadIdx.x;
            float a = 0.f;
            for (int s = 0; s < S_DIM; s++) a += W2[s * H_DIM + j];
            g_w2m[j] = a * (1.f / (float)S_DIM);
        }
        if (threadIdx.x == H_DIM) {
            float a = 0.f;
            for (int s = 0; s < S_DIM; s++) a += b2[s];
            g_b2m = a * (1.f / (float)S_DIM);
        }
    }
}

// ---------------- K1: fused gather + H1 = relu(W1 @ x_v + b1)  [verbatim] --
__global__ void __launch_bounds__(256) k1_gather_gemm1(
    const float* __restrict__ x,  const float* __restrict__ W1,
    const float* __restrict__ b1)
{
    __shared__ __align__(16) float wt[96 * 100];   // [sl][og*12 + k], 38.4 KB
    extern __shared__ __align__(16) float xt[];    // [96][132] = 50.7 KB dyn

    int n0 = blockIdx.x * 128;
    int B  = n0 >> 10;
    int c0 = n0 & 1023;
    int b = B & 15, chunk = B >> 4;
    int ty = (chunk >> 1) * 24, tx = (chunk & 1) * 24;
    int tid = threadIdx.x;
    int nl = tid & 31, og = tid >> 5;

    const float* xb = x + (b * 1024 + c0) * 2304 + ty * 48 + tx;

    float acc[9][4];
#pragma unroll
    for (int k = 0; k < 9; k++)
#pragma unroll
        for (int j = 0; j < 4; j++) acc[k][j] = 0.f;

    for (int t = 0; t < 6; t++) {
        for (int e = tid; e < 96 * 128; e += 256) {
            int cl = e / 96, sl = e - cl * 96;
            int s = t * 96 + sl;
            int si = s / 24, sj = s - si * 24;
            xt[sl * 132 + cl] = xb[cl * 2304 + si * 48 + sj];
        }
        for (int e = tid; e < 72 * 96; e += 256) {
            int o = e / 96, sl = e - o * 96;
            int oq = o / 9, ok = o - oq * 9;
            wt[sl * 100 + oq * 12 + ok] = W1[o * S_DIM + t * 96 + sl];
        }
        __syncthreads();
#pragma unroll 4
        for (int sl = 0; sl < 96; sl++) {
            float4 av = *(const float4*)&xt[sl * 132 + nl * 4];
            const float* wp = &wt[sl * 100 + og * 12];
            float4 w0 = *(const float4*)wp;
            float4 w1 = *(const float4*)(wp + 4);
            float  w8 = wp[8];
            acc[0][0] = fmaf(w0.x, av.x, acc[0][0]); acc[0][1] = fmaf(w0.x, av.y, acc[0][1]);
            acc[0][2] = fmaf(w0.x, av.z, acc[0][2]); acc[0][3] = fmaf(w0.x, av.w, acc[0][3]);
            acc[1][0] = fmaf(w0.y, av.x, acc[1][0]); acc[1][1] = fmaf(w0.y, av.y, acc[1][1]);
            acc[1][2] = fmaf(w0.y, av.z, acc[1][2]); acc[1][3] = fmaf(w0.y, av.w, acc[1][3]);
            acc[2][0] = fmaf(w0.z, av.x, acc[2][0]); acc[2][1] = fmaf(w0.z, av.y, acc[2][1]);
            acc[2][2] = fmaf(w0.z, av.z, acc[2][2]); acc[2][3] = fmaf(w0.z, av.w, acc[2][3]);
            acc[3][0] = fmaf(w0.w, av.x, acc[3][0]); acc[3][1] = fmaf(w0.w, av.y, acc[3][1]);
            acc[3][2] = fmaf(w0.w, av.z, acc[3][2]); acc[3][3] = fmaf(w0.w, av.w, acc[3][3]);
            acc[4][0] = fmaf(w1.x, av.x, acc[4][0]); acc[4][1] = fmaf(w1.x, av.y, acc[4][1]);
            acc[4][2] = fmaf(w1.x, av.z, acc[4][2]); acc[4][3] = fmaf(w1.x, av.w, acc[4][3]);
            acc[5][0] = fmaf(w1.y, av.x, acc[5][0]); acc[5][1] = fmaf(w1.y, av.y, acc[5][1]);
            acc[5][2] = fmaf(w1.y, av.z, acc[5][2]); acc[5][3] = fmaf(w1.y, av.w, acc[5][3]);
            acc[6][0] = fmaf(w1.z, av.x, acc[6][0]); acc[6][1] = fmaf(w1.z, av.y, acc[6][1]);
            acc[6][2] = fmaf(w1.z, av.z, acc[6][2]); acc[6][3] = fmaf(w1.z, av.w, acc[6][3]);
            acc[7][0] = fmaf(w1.w, av.x, acc[7][0]); acc[7][1] = fmaf(w1.w, av.y, acc[7][1]);
            acc[7][2] = fmaf(w1.w, av.z, acc[7][2]); acc[7][3] = fmaf(w1.w, av.w, acc[7][3]);
            acc[8][0] = fmaf(w8,   av.x, acc[8][0]); acc[8][1] = fmaf(w8,   av.y, acc[8][1]);
            acc[8][2] = fmaf(w8,   av.z, acc[8][2]); acc[8][3] = fmaf(w8,   av.w, acc[8][3]);
        }
        __syncthreads();
    }
#pragma unroll
    for (int k = 0; k < 9; k++) {
        int o = og * 9 + k;
        float bb = b1[o];
        float4 v;
        v.x = fmaxf(acc[k][0] + bb, 0.f);
        v.y = fmaxf(acc[k][1] + bb, 0.f);
        v.z = fmaxf(acc[k][2] + bb, 0.f);
        v.w = fmaxf(acc[k][3] + bb, 0.f);
        *(float4*)&g_H1[o * N_TOT + n0 + nl * 4] = v;
    }
}

// ---------------- K2a: xm = w2m @ H1 + b2m  [verbatim] ---------------------
__global__ void __launch_bounds__(256) k2a_xm(void)
{
    __shared__ float w2ms[H_DIM];
    int tid = threadIdx.x;
    if (tid < H_DIM) w2ms[tid] = g_w2m[tid];
    __syncthreads();

    int n = blockIdx.x * 256 + tid;
    float h[H_DIM];
#pragma unroll
    for (int p = 0; p < H_DIM; p++) h[p] = g_H1[p * N_TOT + n];

    float xm = g_b2m;
#pragma unroll
    for (int p = 0; p < H_DIM; p++) xm = fmaf(w2ms[p], h[p], xm);
    g_xm[n] = xm;
}

// ---------------- K2b: per-group moments + R_t = M@P_t + yb m_t [verbatim] -
__global__ void __launch_bounds__(256) k2b_moments(void)
{
    extern __shared__ __align__(16) float sm[];
    float* hs  = sm;                    // [73][516]  (row 72 = ones)
    float* qs  = sm + 73 * 516;         // [512][12]  (col 11 zeroed)
    float* ps  = sm + 73 * 516 + 512 * 12;   // [73][12]
    float* Ms  = ps + 73 * 12;          // [72][72]
    float* ybs = Ms + 72 * 72;          // [72]

    int g = blockIdx.x;
    int nb = g * 512;
    int tid = threadIdx.x;

    for (int e = tid; e < 73 * 128; e += 256) {
        int j = e >> 7, c4 = e & 127;
        float4 v = (j < H_DIM)
            ? *(const float4*)&g_H1[j * N_TOT + nb + c4 * 4]
            : make_float4(1.f, 1.f, 1.f, 1.f);
        *(float4*)&hs[j * 516 + c4 * 4] = v;
    }
    for (int e = tid; e < H_DIM * H_DIM; e += 256) Ms[e] = g_M[e];
    if (tid < H_DIM) ybs[tid] = g_yb[tid];

    for (int c = tid; c < 512; c += 256) {
        float xm = g_xm[nb + c];
        float a = __expf(-xm * xm);
        float p = a;
#pragma unroll
        for (int t = 0; t < NT; t++) { qs[c * 12 + t] = p; p *= xm; }
        qs[c * 12 + NT] = 0.f;
    }
    __syncthreads();

    if (tid < 219) {
        int j = tid / 3, tg = tid - 3 * (tid / 3);
        int t0 = tg * 4;
        float a0 = 0.f, a1 = 0.f, a2 = 0.f, a3 = 0.f;
        const float* hrow = &hs[j * 516];
        for (int c = 0; c < 512; c++) {
            float hv = hrow[c];
            float4 qv = *(const float4*)&qs[c * 12 + t0];
            a0 = fmaf(hv, qv.x, a0);
            a1 = fmaf(hv, qv.y, a1);
            a2 = fmaf(hv, qv.z, a2);
            a3 = fmaf(hv, qv.w, a3);
        }
        ps[j * 12 + t0 + 0] = a0;
        ps[j * 12 + t0 + 1] = a1;
        ps[j * 12 + t0 + 2] = a2;
        if (tg < 2) ps[j * 12 + t0 + 3] = a3;
        else        ps[j * 12 + 11]     = 0.f;
    }
    __syncthreads();

    if (tid < 216) {
        int j = tid / 3, tg = tid - 3 * (tid / 3);
        int t0 = tg * 4;
        float a0 = 0.f, a1 = 0.f, a2 = 0.f, a3 = 0.f;
        for (int p = 0; p < H_DIM; p++) {
            float mv = Ms[j * H_DIM + p];
            float4 pv = *(const float4*)&ps[p * 12 + t0];
            a0 = fmaf(mv, pv.x, a0);
            a1 = fmaf(mv, pv.y, a1);
            a2 = fmaf(mv, pv.z, a2);
            a3 = fmaf(mv, pv.w, a3);
        }
        float yv = ybs[j];
        float4 mm = *(const float4*)&ps[72 * 12 + t0];
        a0 = fmaf(yv, mm.x, a0);
        a1 = fmaf(yv, mm.y, a1);
        a2 = fmaf(yv, mm.z, a2);
        a3 = fmaf(yv, mm.w, a3);
        float* rp = &g_R[(g * 73 + j) * 12 + t0];
        rp[0] = a0; rp[1] = a1; rp[2] = a2;
        if (tg < 2) rp[3] = a3;
    } else if (tid < 219) {
        int tg = tid - 216;
        int t0 = tg * 4;
        int nt = (tg == 2) ? 3 : 4;
        for (int i = 0; i < nt; i++)
            g_R[(g * 73 + 72) * 12 + t0 + i] = ps[72 * 12 + t0 + i];
    }
}

// ---------------- K4c: H2[j,d] = relu(b3 + (sum_t w_t R_t[j]) / U_d) -------
__global__ void __launch_bounds__(256) k4_combine(const float* __restrict__ b3)
{
    __shared__ __align__(16) float Rs[73 * 12];
    __shared__ float b3s[H_DIM];
    int g = blockIdx.x >> 1;
    int d = blockIdx.x * 256 + threadIdx.x;
    int tid = threadIdx.x;

    for (int e = tid; e < 73 * 12; e += 256) Rs[e] = g_R[g * 73 * 12 + e];
    if (tid < H_DIM) b3s[tid] = b3[tid];
    __syncthreads();

    float xm = g_xm[d];
    float w[NT];
    w[0] = 1.f;
    w[1] = 2.f * xm;
    w[2] = w[1] * xm;
    w[3] = w[2] * xm * (2.f / 3.f);
    w[4] = w[3] * xm * 0.5f;
    w[5] = w[4] * xm * 0.4f;
    w[6] = w[5] * xm * (1.f / 3.f);
    w[7] = w[6] * xm * (2.f / 7.f);
    w[8] = w[7] * xm * 0.25f;
    w[9] = w[8] * xm * (2.f / 9.f);
    w[10] = w[9] * xm * 0.2f;

    float U = 0.f;
#pragma unroll
    for (int t = 0; t < NT; t++) U = fmaf(w[t], Rs[72 * 12 + t], U);
    float invU = 1.f / U;

#pragma unroll 8
    for (int j = 0; j < H_DIM; j++) {
        float s = 0.f;
#pragma unroll
        for (int t = 0; t < NT; t++) s = fmaf(w[t], Rs[j * 12 + t], s);
        g_H2[j * N_TOT + d] = fmaxf(fmaf(s, invU, b3s[j]), 0.f);
    }
}

// ---------------- K5a: SYRK partials  G = H2@H2^T, hsum  [R5-validated] ----
__global__ void __launch_bounds__(288) k5a_syrk(void)
{
    __shared__ __align__(16) float hs[72 * 20];   // [p][16 n + pad]
    int tid = threadIdx.x;
    int i = tid >> 2, jq = tid & 3;
    int n0 = blockIdx.x * 1024;

    float acc[18];
#pragma unroll
    for (int k = 0; k < 18; k++) acc[k] = 0.f;
    float hb = 0.f;

    for (int it = 0; it < 64; it++) {
        int base = n0 + it * 16;
        {
            int p = tid >> 2, q = tid & 3;
            *(float4*)&hs[p * 20 + q * 4] =
                *(const float4*)&g_H2[p * N_TOT + base + q * 4];
        }
        __syncthreads();
#pragma unroll
        for (int q = 0; q < 4; q++) {
            float4 hi = *(const float4*)&hs[i * 20 + q * 4];
#pragma unroll
            for (int k = 0; k < 18; k++) {
                float4 hj = *(const float4*)&hs[(jq * 18 + k) * 20 + q * 4];
                float a = acc[k];
                a = fmaf(hi.x, hj.x, a);
                a = fmaf(hi.y, hj.y, a);
                a = fmaf(hi.z, hj.z, a);
                a = fmaf(hi.w, hj.w, a);
                acc[k] = a;
            }
            if (jq == 0) hb += (hi.x + hi.y) + (hi.z + hi.w);
        }
        __syncthreads();
    }
#pragma unroll
    for (int k = 0; k < 18; k++)
        g_Gpart[blockIdx.x * (H_DIM * H_DIM) + i * H_DIM + jq * 18 + k] = acc[k];
    if (jq == 0) g_hpart[blockIdx.x * H_DIM + i] = hb;
}

// ---------------- K5b: deterministic reduction of partials  [R5-validated] -
__global__ void __launch_bounds__(256) k5b_reduce(void)
{
    int idx = blockIdx.x * 256 + threadIdx.x;
    if (idx < H_DIM * H_DIM) {
        float a = 0.f;
        for (int b = 0; b < 64; b++) a += g_Gpart[b * (H_DIM * H_DIM) + idx];
        g_G[idx] = a;
    } else if (idx < H_DIM * H_DIM + H_DIM) {
        int i = idx - H_DIM * H_DIM;
        float a = 0.f;
        for (int b = 0; b < 64; b++) a += g_hpart[b * H_DIM + i];
        g_hsum[i] = a;
    }
}

// ---------------- K6: per-s BN scale/shift from G, hsum  [R5-validated] ----
__global__ void __launch_bounds__(96) k6_stats(
    const float* __restrict__ W4, const float* __restrict__ b4,
    const float* __restrict__ gamma, const float* __restrict__ beta)
{
    __shared__ float Gs[H_DIM * H_DIM];
    __shared__ float w[H_DIM];
    __shared__ float r1[96], r2[96];
    int s = blockIdx.x;
    int tid = threadIdx.x;
    for (int e = tid; e < H_DIM * H_DIM; e += 96) Gs[e] = g_G[e];
    if (tid < H_DIM) w[tid] = W4[s * H_DIM + tid];
    __syncthreads();

    float t1 = 0.f, t2 = 0.f;
    if (tid < H_DIM) {
        float rd = 0.f;
        for (int q = 0; q < H_DIM; q++) rd = fmaf(Gs[tid * H_DIM + q], w[q], rd);
        t1 = w[tid] * rd;
        t2 = w[tid] * g_hsum[tid];
    }
    r1[tid] = t1; r2[tid] = t2;
    __syncthreads();
    if (tid == 0) {
        float wgw = 0.f, wh = 0.f;
        for (int p = 0; p < H_DIM; p++) { wgw += r1[p]; wh += r2[p]; }
        const float invN = 1.f / (float)N_TOT;
        float bb = b4[s];
        float mu = wh * invN + bb;
        float e2 = wgw * invN + 2.f * bb * wh * invN + bb * bb;
        float var = e2 - mu * mu;
        float rstd = rsqrtf(var + 1e-5f);
        g_scale[s] = rstd * gamma[s] * 0.25f;
        g_shift[s] = beta[s] * 0.25f + (bb - mu) * rstd * gamma[s] * 0.25f;
    }
}

// ---------------- K57 v2: out GEMM + BN + scatter, NO out2 -----------------
// grid (9 sc, 16 ct, 64 B), block 256 = 16 cl x 16 sg; 38.8 KB -> 4 blk/SM
// one GEMM phase (64s x 64c tile, thread 4x4), one k7v2-style scatter phase.
// g_out2 never exists; scale/shift precomputed from SYRK stats (b4 folded).
__global__ void __launch_bounds__(256) k57_gemm_scatter(
    const float* __restrict__ x, const float* __restrict__ W4,
    float* __restrict__ out)
{
    extern __shared__ __align__(16) float sm[];
    float* h2t = sm;                   // [72][68] GEMM input; aliased after
    float* ws  = sm + 72 * 68;         // [64][73]
    float* scs = ws + 64 * 73;         // [64]
    float* shs = scs + 64;             // [64]

    int s0 = blockIdx.x * 64;
    int c0 = blockIdx.y * 64;
    int B  = blockIdx.z;
    int n0 = B * 1024 + c0;
    int tid = threadIdx.x;
    int cl = tid & 15, sg = tid >> 4;

    for (int e = tid; e < 72 * 16; e += 256) {
        int p = e >> 4, c4 = e & 15;
        *(float4*)&h2t[p * 68 + c4 * 4] =
            *(const float4*)&g_H2[p * N_TOT + n0 + c4 * 4];
    }
    for (int e = tid; e < 64 * H_DIM; e += 256) {
        int j = e / H_DIM, p = e - j * H_DIM;
        ws[j * 73 + p] = W4[(s0 + j) * H_DIM + p];
    }
    if (tid < 64) { scs[tid] = g_scale[s0 + tid]; shs[tid] = g_shift[s0 + tid]; }
    __syncthreads();

    float acc[4][4];
#pragma unroll
    for (int k = 0; k < 4; k++)
#pragma unroll
        for (int j = 0; j < 4; j++) acc[k][j] = 0.f;

#pragma unroll 4
    for (int p = 0; p < H_DIM; p++) {
        float4 av = *(const float4*)&h2t[p * 68 + cl * 4];
#pragma unroll
        for (int k = 0; k < 4; k++) {
            float w = ws[(sg * 4 + k) * 73 + p];
            acc[k][0] = fmaf(w, av.x, acc[k][0]);
            acc[k][1] = fmaf(w, av.y, acc[k][1]);
            acc[k][2] = fmaf(w, av.z, acc[k][2]);
            acc[k][3] = fmaf(w, av.w, acc[k][3]);
        }
    }
    __syncthreads();                   // all h2t reads done -> safe to alias

    // normalize + stage into two [64][33] half-tiles aliasing h2t
    float* t0 = h2t;                   // c 0..31
    float* t1 = h2t + 64 * 33;         // c 32..63
    {
        int ch = cl * 4;
        float* tb = (ch < 32) ? t0 : t1;
        int cc = ch & 31;
#pragma unroll
        for (int k = 0; k < 4; k++) {
            int sl = sg * 4 + k;
            float sc = scs[sl], sh = shs[sl];
            float* tp = &tb[sl * 33 + cc];
            tp[0] = fmaf(acc[k][0], sc, sh);
            tp[1] = fmaf(acc[k][1], sc, sh);
            tp[2] = fmaf(acc[k][2], sc, sh);
            tp[3] = fmaf(acc[k][3], sc, sh);
        }
    }
    __syncthreads();

    int b = B & 15, chunk = B >> 4;
    int ty = (chunk >> 1) * 24, tx = (chunk & 1) * 24;
    const float* xb = x   + (b * 1024 + c0) * 2304 + ty * 48 + tx;
    float*       ob = out + (b * 1024 + c0) * 2304 + ty * 48 + tx;

    // 1024 float4 outputs: c = e>>4 (0..63), sl = (e&15)*4; sj 4-aligned
#pragma unroll
    for (int e = tid; e < 1024; e += 256) {
        int c = e >> 4, slq = e & 15;
        int sl = slq * 4;
        int s = s0 + sl;
        int si = s / 24, sj = s - si * 24;
        int addr = c * 2304 + si * 48 + sj;
        const float* tb = (c < 32) ? t0 : t1;
        int cc = c & 31;
        float4 xv = *(const float4*)&xb[addr];
        float v0 = tb[(sl + 0) * 33 + cc];
        float v1 = tb[(sl + 1) * 33 + cc];
        float v2 = tb[(sl + 2) * 33 + cc];
        float v3 = tb[(sl + 3) * 33 + cc];
        float4 o;
        o.x = fmaxf(xv.x + v0, 0.f);
        o.y = fmaxf(xv.y + v1, 0.f);
        o.z = fmaxf(xv.z + v2, 0.f);
        o.w = fmaxf(xv.w + v3, 0.f);
        *(float4*)&ob[addr] = o;
    }
}

// ---------------- host launch ---------------------------------------------
extern "C" void kernel_launch(void* const* d_in, const int* in_sizes, int n_in,
                              void* d_out, int out_size)
{
    const float* x     = (const float*)d_in[0];
    const float* w1    = (const float*)d_in[1];
    const float* b1    = (const float*)d_in[2];
    const float* w2    = (const float*)d_in[3];
    const float* b2    = (const float*)d_in[4];
    const float* w3    = (const float*)d_in[5];
    const float* b3    = (const float*)d_in[6];
    const float* w4    = (const float*)d_in[7];
    const float* b4    = (const float*)d_in[8];
    const float* gamma = (const float*)d_in[9];
    const float* beta  = (const float*)d_in[10];
    float* out = (float*)d_out;

    const int K2B_SMEM = (73 * 516 + 512 * 12 + 73 * 12 + 72 * 72 + 72) * 4;
    const int K57_SMEM = (72 * 68 + 64 * 73 + 128) * 4;

    cudaFuncSetAttribute(k1_gather_gemm1, cudaFuncAttributeMaxDynamicSharedMemorySize,
                         96 * 132 * 4);
    cudaFuncSetAttribute(k2b_moments, cudaFuncAttributeMaxDynamicSharedMemorySize,
                         K2B_SMEM);
    cudaFuncSetAttribute(k57_gemm_scatter, cudaFuncAttributeMaxDynamicSharedMemorySize,
                         K57_SMEM);

    k0_prep<<<74, 128>>>(w2, b2, w3);
    k1_gather_gemm1<<<512, 256, 96 * 132 * 4>>>(x, w1, b1);
    k2a_xm<<<256, 256>>>();
    k2b_moments<<<128, 256, K2B_SMEM>>>();     // 4th launch -> ncu capture
    k4_combine<<<256, 256>>>(b3);
    k5a_syrk<<<64, 288>>>();
    k5b_reduce<<<21, 256>>>();
    k6_stats<<<S_DIM, 96>>>(w4, b4, gamma, beta);
    k57_gemm_scatter<<<dim3(9, 16, 64), 256, K57_SMEM>>>(x, w4, out);
}

// round 16
// speedup vs baseline: 1.1466x; 1.1466x over previous
#include <cuda_runtime.h>
#include <math.h>

#define N_TOT 65536      // B(64) * C(1024) columns
#define S_DIM 576
#define H_DIM 72
#define NT 11            // Taylor terms t = 0..10 of exp(2 xm_c xm_d)

// ---------------- scratch (device globals; no allocation allowed) ----------
__device__ float g_H1[H_DIM * N_TOT];          // 18.9 MB
__device__ float g_H2[H_DIM * N_TOT];          // 18.9 MB
__device__ float g_xm[N_TOT];
__device__ float g_out2[S_DIM * N_TOT];        // 151 MB
__device__ float g_psum[S_DIM * 512];          // BN partials per (s, ntile)
__device__ float g_psq [S_DIM * 512];
__device__ float g_R[128 * 73 * 12];           // per-group R_t (row 72 = m_t)
__device__ float g_M[H_DIM * H_DIM];
__device__ float g_yb[H_DIM];
__device__ float g_w2m[H_DIM];
__device__ float g_b2m;
__device__ float g_scale[S_DIM];
__device__ float g_shift[S_DIM];

// ---------------- K01: prep (blocks 0..73) + gemm1 (74..585) ---------------
// prep: M = W3@W2 (0..71), yb = W3@b2 (72), w2m/b2m (73)
// gemm: fused gather + H1 = relu(W1 @ x_v + b1)  [R13 k1 body verbatim]
__global__ void __launch_bounds__(256) k01_prep_gemm1(
    const float* __restrict__ x,  const float* __restrict__ W1,
    const float* __restrict__ b1, const float* __restrict__ W2,
    const float* __restrict__ b2, const float* __restrict__ W3)
{
    __shared__ float row[S_DIM];
    __shared__ __align__(16) float wt[96 * 100];   // [sl][og*12 + k], 38.4 KB
    extern __shared__ __align__(16) float xt[];    // [96][132] = 50.7 KB dyn

    if (blockIdx.x < 74) {
        int o = blockIdx.x;
        if (o < H_DIM) {
            for (int e = threadIdx.x; e < S_DIM; e += 256) row[e] = W3[o * S_DIM + e];
            __syncthreads();
            if (threadIdx.x < H_DIM) {
                int j = threadIdx.x;
                float a = 0.f;
                for (int s = 0; s < S_DIM; s++) a = fmaf(row[s], W2[s * H_DIM + j], a);
                g_M[o * H_DIM + j] = a;
            }
        } else if (o == H_DIM) {
            for (int e = threadIdx.x; e < S_DIM; e += 256) row[e] = b2[e];
            __syncthreads();
            if (threadIdx.x < H_DIM) {
                int oo = threadIdx.x;
                float a = 0.f;
                for (int s = 0; s < S_DIM; s++) a = fmaf(W3[oo * S_DIM + s], row[s], a);
                g_yb[oo] = a;
            }
        } else {
            if (threadIdx.x < H_DIM) {
                int j = threadIdx.x;
                float a = 0.f;
                for (int s = 0; s < S_DIM; s++) a += W2[s * H_DIM + j];
                g_w2m[j] = a * (1.f / (float)S_DIM);
            }
            if (threadIdx.x == H_DIM) {
                float a = 0.f;
                for (int s = 0; s < S_DIM; s++) a += b2[s];
                g_b2m = a * (1.f / (float)S_DIM);
            }
        }
        return;
    }

    int n0 = (blockIdx.x - 74) * 128;
    int B  = n0 >> 10;
    int c0 = n0 & 1023;
    int b = B & 15, chunk = B >> 4;
    int ty = (chunk >> 1) * 24, tx = (chunk & 1) * 24;
    int tid = threadIdx.x;
    int nl = tid & 31, og = tid >> 5;

    const float* xb = x + (b * 1024 + c0) * 2304 + ty * 48 + tx;

    float acc[9][4];
#pragma unroll
    for (int k = 0; k < 9; k++)
#pragma unroll
        for (int j = 0; j < 4; j++) acc[k][j] = 0.f;

    for (int t = 0; t < 6; t++) {
        for (int e = tid; e < 96 * 128; e += 256) {
            int cl = e / 96, sl = e - cl * 96;
            int s = t * 96 + sl;
            int si = s / 24, sj = s - si * 24;
            xt[sl * 132 + cl] = xb[cl * 2304 + si * 48 + sj];
        }
        for (int e = tid; e < 72 * 96; e += 256) {
            int o = e / 96, sl = e - o * 96;
            int oq = o / 9, ok = o - oq * 9;
            wt[sl * 100 + oq * 12 + ok] = W1[o * S_DIM + t * 96 + sl];
        }
        __syncthreads();
#pragma unroll 4
        for (int sl = 0; sl < 96; sl++) {
            float4 av = *(const float4*)&xt[sl * 132 + nl * 4];
            const float* wp = &wt[sl * 100 + og * 12];
            float4 w0 = *(const float4*)wp;
            float4 w1 = *(const float4*)(wp + 4);
            float  w8 = wp[8];
            acc[0][0] = fmaf(w0.x, av.x, acc[0][0]); acc[0][1] = fmaf(w0.x, av.y, acc[0][1]);
            acc[0][2] = fmaf(w0.x, av.z, acc[0][2]); acc[0][3] = fmaf(w0.x, av.w, acc[0][3]);
            acc[1][0] = fmaf(w0.y, av.x, acc[1][0]); acc[1][1] = fmaf(w0.y, av.y, acc[1][1]);
            acc[1][2] = fmaf(w0.y, av.z, acc[1][2]); acc[1][3] = fmaf(w0.y, av.w, acc[1][3]);
            acc[2][0] = fmaf(w0.z, av.x, acc[2][0]); acc[2][1] = fmaf(w0.z, av.y, acc[2][1]);
            acc[2][2] = fmaf(w0.z, av.z, acc[2][2]); acc[2][3] = fmaf(w0.z, av.w, acc[2][3]);
            acc[3][0] = fmaf(w0.w, av.x, acc[3][0]); acc[3][1] = fmaf(w0.w, av.y, acc[3][1]);
            acc[3][2] = fmaf(w0.w, av.z, acc[3][2]); acc[3][3] = fmaf(w0.w, av.w, acc[3][3]);
            acc[4][0] = fmaf(w1.x, av.x, acc[4][0]); acc[4][1] = fmaf(w1.x, av.y, acc[4][1]);
            acc[4][2] = fmaf(w1.x, av.z, acc[4][2]); acc[4][3] = fmaf(w1.x, av.w, acc[4][3]);
            acc[5][0] = fmaf(w1.y, av.x, acc[5][0]); acc[5][1] = fmaf(w1.y, av.y, acc[5][1]);
            acc[5][2] = fmaf(w1.y, av.z, acc[5][2]); acc[5][3] = fmaf(w1.y, av.w, acc[5][3]);
            acc[6][0] = fmaf(w1.z, av.x, acc[6][0]); acc[6][1] = fmaf(w1.z, av.y, acc[6][1]);
            acc[6][2] = fmaf(w1.z, av.z, acc[6][2]); acc[6][3] = fmaf(w1.z, av.w, acc[6][3]);
            acc[7][0] = fmaf(w1.w, av.x, acc[7][0]); acc[7][1] = fmaf(w1.w, av.y, acc[7][1]);
            acc[7][2] = fmaf(w1.w, av.z, acc[7][2]); acc[7][3] = fmaf(w1.w, av.w, acc[7][3]);
            acc[8][0] = fmaf(w8,   av.x, acc[8][0]); acc[8][1] = fmaf(w8,   av.y, acc[8][1]);
            acc[8][2] = fmaf(w8,   av.z, acc[8][2]); acc[8][3] = fmaf(w8,   av.w, acc[8][3]);
        }
        __syncthreads();
    }
#pragma unroll
    for (int k = 0; k < 9; k++) {
        int o = og * 9 + k;
        float bb = b1[o];
        float4 v;
        v.x = fmaxf(acc[k][0] + bb, 0.f);
        v.y = fmaxf(acc[k][1] + bb, 0.f);
        v.z = fmaxf(acc[k][2] + bb, 0.f);
        v.w = fmaxf(acc[k][3] + bb, 0.f);
        *(float4*)&g_H1[o * N_TOT + n0 + nl * 4] = v;
    }
}

// ---------------- K2ab: fused xm + per-group moments + R_t -----------------
// grid 128 (one per 512-col group). xm computed from the resident H1 tile
// (saves k2a's separate 19 MB H1 pass), then q powers / P / R as in R13.
__global__ void __launch_bounds__(256) k2ab_moments(void)
{
    extern __shared__ __align__(16) float sm[];
    float* hs   = sm;                        // [73][516]  (row 72 = ones)
    float* qs   = hs + 73 * 516;             // [512][12]  (col 11 zeroed)
    float* ps   = qs + 512 * 12;             // [73][12]
    float* Ms   = ps + 73 * 12;              // [72][72]
    float* ybs  = Ms + 72 * 72;              // [72]
    float* w2ms = ybs + 72;                  // [72]
    float* xms  = w2ms + 72;                 // [512]

    int g = blockIdx.x;
    int nb = g * 512;
    int tid = threadIdx.x;

    // phase 1: H1 group tile (+ones row), M, yb, w2m
    for (int e = tid; e < 73 * 128; e += 256) {
        int j = e >> 7, c4 = e & 127;
        float4 v = (j < H_DIM)
            ? *(const float4*)&g_H1[j * N_TOT + nb + c4 * 4]
            : make_float4(1.f, 1.f, 1.f, 1.f);
        *(float4*)&hs[j * 516 + c4 * 4] = v;
    }
    for (int e = tid; e < H_DIM * H_DIM; e += 256) Ms[e] = g_M[e];
    if (tid < H_DIM) { ybs[tid] = g_yb[tid]; w2ms[tid] = g_w2m[tid]; }
    __syncthreads();

    // phase 2: xm from resident tile, then q powers
    for (int c = tid; c < 512; c += 256) {
        float xm = g_b2m;
#pragma unroll 8
        for (int p = 0; p < H_DIM; p++) xm = fmaf(w2ms[p], hs[p * 516 + c], xm);
        xms[c] = xm;
        g_xm[nb + c] = xm;
        float a = __expf(-xm * xm);
        float pw = a;
#pragma unroll
        for (int t = 0; t < NT; t++) { qs[c * 12 + t] = pw; pw *= xm; }
        qs[c * 12 + NT] = 0.f;
    }
    __syncthreads();

    // phase 3: P[j][t] = sum_c hs[j][c] * qs[c][t]
    if (tid < 219) {
        int j = tid / 3, tg = tid - 3 * (tid / 3);
        int t0 = tg * 4;
        float a0 = 0.f, a1 = 0.f, a2 = 0.f, a3 = 0.f;
        const float* hrow = &hs[j * 516];
        for (int c = 0; c < 512; c++) {
            float hv = hrow[c];
            float4 qv = *(const float4*)&qs[c * 12 + t0];
            a0 = fmaf(hv, qv.x, a0);
            a1 = fmaf(hv, qv.y, a1);
            a2 = fmaf(hv, qv.z, a2);
            a3 = fmaf(hv, qv.w, a3);
        }
        ps[j * 12 + t0 + 0] = a0;
        ps[j * 12 + t0 + 1] = a1;
        ps[j * 12 + t0 + 2] = a2;
        if (tg < 2) ps[j * 12 + t0 + 3] = a3;
        else        ps[j * 12 + 11]     = 0.f;
    }
    __syncthreads();

    // phase 4: R[j][t] = M[j]·P[:,t] + yb[j]*m[t];  R row 72 = m
    if (tid < 216) {
        int j = tid / 3, tg = tid - 3 * (tid / 3);
        int t0 = tg * 4;
        float a0 = 0.f, a1 = 0.f, a2 = 0.f, a3 = 0.f;
        for (int p = 0; p < H_DIM; p++) {
            float mv = Ms[j * H_DIM + p];
            float4 pv = *(const float4*)&ps[p * 12 + t0];
            a0 = fmaf(mv, pv.x, a0);
            a1 = fmaf(mv, pv.y, a1);
            a2 = fmaf(mv, pv.z, a2);
            a3 = fmaf(mv, pv.w, a3);
        }
        float yv = ybs[j];
        float4 mm = *(const float4*)&ps[72 * 12 + t0];
        a0 = fmaf(yv, mm.x, a0);
        a1 = fmaf(yv, mm.y, a1);
        a2 = fmaf(yv, mm.z, a2);
        a3 = fmaf(yv, mm.w, a3);
        float* rp = &g_R[(g * 73 + j) * 12 + t0];
        rp[0] = a0; rp[1] = a1; rp[2] = a2;
        if (tg < 2) rp[3] = a3;
    } else if (tid < 219) {
        int tg = tid - 216;
        int t0 = tg * 4;
        int nt = (tg == 2) ? 3 : 4;
        for (int i = 0; i < nt; i++)
            g_R[(g * 73 + 72) * 12 + t0 + i] = ps[72 * 12 + t0 + i];
    }
}

// ---------------- K4c: H2[j,d] = relu(b3 + (sum_t w_t R_t[j]) / U_d) -------
__global__ void __launch_bounds__(256) k4_combine(const float* __restrict__ b3)
{
    __shared__ __align__(16) float Rs[73 * 12];
    __shared__ float b3s[H_DIM];
    int g = blockIdx.x >> 1;
    int d = blockIdx.x * 256 + threadIdx.x;
    int tid = threadIdx.x;

    for (int e = tid; e < 73 * 12; e += 256) Rs[e] = g_R[g * 73 * 12 + e];
    if (tid < H_DIM) b3s[tid] = b3[tid];
    __syncthreads();

    float xm = g_xm[d];
    float w[NT];
    w[0] = 1.f;
    w[1] = 2.f * xm;
    w[2] = w[1] * xm;
    w[3] = w[2] * xm * (2.f / 3.f);
    w[4] = w[3] * xm * 0.5f;
    w[5] = w[4] * xm * 0.4f;
    w[6] = w[5] * xm * (1.f / 3.f);
    w[7] = w[6] * xm * (2.f / 7.f);
    w[8] = w[7] * xm * 0.25f;
    w[9] = w[8] * xm * (2.f / 9.f);
    w[10] = w[9] * xm * 0.2f;

    float U = 0.f;
#pragma unroll
    for (int t = 0; t < NT; t++) U = fmaf(w[t], Rs[72 * 12 + t], U);
    float invU = 1.f / U;

#pragma unroll 8
    for (int j = 0; j < H_DIM; j++) {
        float s = 0.f;
#pragma unroll
        for (int t = 0; t < NT; t++) s = fmaf(w[t], Rs[j * 12 + t], s);
        g_H2[j * N_TOT + d] = fmaxf(fmaf(s, invU, b3s[j]), 0.f);
    }
}

// ---------------- K5: out2 = W4 @ H2 + b4  + fused BN partials  [verbatim] -
// 4th launch this round -> FIRST ncu capture of this kernel
__global__ void __launch_bounds__(256) k5_out2(const float* __restrict__ W4,
                                               const float* __restrict__ b4)
{
    extern __shared__ float ht[];                  // [72][128] = 36864 B
    __shared__ float ws[64 * 73];                  // [j][p + pad]
    __shared__ float b4s[64];
    int n0 = blockIdx.x * 128;
    int s0 = blockIdx.y * 64;
    int tid = threadIdx.x;
    int nl = tid & 31, sg = tid >> 5;

    for (int e = tid; e < H_DIM * 128; e += 256) {
        int p = e >> 7, cl = e & 127;
        ht[e] = g_H2[p * N_TOT + n0 + cl];
    }
    for (int e = tid; e < 64 * H_DIM; e += 256) {
        int j = e / H_DIM, p = e - j * H_DIM;
        ws[j * 73 + p] = W4[(s0 + j) * H_DIM + p];
    }
    if (tid < 64) b4s[tid] = b4[s0 + tid];
    __syncthreads();

    float acc[8][4];
#pragma unroll
    for (int k = 0; k < 8; k++)
#pragma unroll
        for (int j = 0; j < 4; j++) acc[k][j] = 0.f;

#pragma unroll 4
    for (int p = 0; p < H_DIM; p++) {
        float4 av = *(const float4*)&ht[p * 128 + nl * 4];
#pragma unroll
        for (int k = 0; k < 8; k++) {
            float w = ws[(sg * 8 + k) * 73 + p];
            acc[k][0] = fmaf(w, av.x, acc[k][0]);
            acc[k][1] = fmaf(w, av.y, acc[k][1]);
            acc[k][2] = fmaf(w, av.z, acc[k][2]);
            acc[k][3] = fmaf(w, av.w, acc[k][3]);
        }
    }
#pragma unroll
    for (int k = 0; k < 8; k++) {
        int s = s0 + sg * 8 + k;
        float bb = b4s[sg * 8 + k];
        float4 v;
        v.x = acc[k][0] + bb; v.y = acc[k][1] + bb;
        v.z = acc[k][2] + bb; v.w = acc[k][3] + bb;
        *(float4*)&g_out2[s * N_TOT + n0 + nl * 4] = v;

        float sm = (v.x + v.y) + (v.z + v.w);
        float sq = (v.x * v.x + v.y * v.y) + (v.z * v.z + v.w * v.w);
#pragma unroll
        for (int off = 16; off; off >>= 1) {
            sm += __shfl_down_sync(0xffffffffu, sm, off);
            sq += __shfl_down_sync(0xffffffffu, sq, off);
        }
        if (nl == 0) {
            g_psum[s * 512 + blockIdx.x] = sm;
            g_psq [s * 512 + blockIdx.x] = sq;
        }
    }
}

// ---------------- K6r: reduce BN partials -> scale/shift  [verbatim] -------
__global__ void __launch_bounds__(256) k6_reduce(const float* __restrict__ gamma,
                                                 const float* __restrict__ beta)
{
    __shared__ float s1[8], s2[8];
    int s = blockIdx.x;
    int tid = threadIdx.x;
    float a = 0.f, q = 0.f;
    for (int i = tid; i < 512; i += 256) {
        a += g_psum[s * 512 + i];
        q += g_psq [s * 512 + i];
    }
#pragma unroll
    for (int off = 16; off; off >>= 1) {
        a += __shfl_down_sync(0xffffffffu, a, off);
        q += __shfl_down_sync(0xffffffffu, q, off);
    }
    int w = tid >> 5, l = tid & 31;
    if (l == 0) { s1[w] = a; s2[w] = q; }
    __syncthreads();
    if (tid == 0) {
        float aa = 0.f, qq = 0.f;
        for (int i = 0; i < 8; i++) { aa += s1[i]; qq += s2[i]; }
        float mu = aa * (1.f / (float)N_TOT);
        float var = qq * (1.f / (float)N_TOT) - mu * mu;
        float rstd = rsqrtf(var + 1e-5f);
        float ga = gamma[s];
        g_scale[s] = rstd * ga * 0.25f;
        g_shift[s] = (beta[s] - mu * rstd * ga) * 0.25f;
    }
}

// ---------------- K7 v2: vectorized normalize + scatter  [verbatim] --------
__global__ void __launch_bounds__(256) k7_final(
    const float* __restrict__ x, float* __restrict__ out)
{
    __shared__ float tile[64 * 33];
    __shared__ float scs[64], shs[64];
    int s0 = blockIdx.x * 64;
    int c0 = blockIdx.y * 32;
    int B  = blockIdx.z;
    int n0 = B * 1024 + c0;
    int tid = threadIdx.x;

    if (tid < 64) { scs[tid] = g_scale[s0 + tid]; shs[tid] = g_shift[s0 + tid]; }
    __syncthreads();

#pragma unroll
    for (int e = tid; e < 512; e += 256) {
        int sl = e >> 3, cl4 = e & 7;
        float4 v = *(const float4*)&g_out2[(s0 + sl) * N_TOT + n0 + cl4 * 4];
        float sc = scs[sl], sh = shs[sl];
        float* tp = &tile[sl * 33 + cl4 * 4];
        tp[0] = fmaf(v.x, sc, sh);
        tp[1] = fmaf(v.y, sc, sh);
        tp[2] = fmaf(v.z, sc, sh);
        tp[3] = fmaf(v.w, sc, sh);
    }
    __syncthreads();

    int b = B & 15, chunk = B >> 4;
    int ty = (chunk >> 1) * 24, tx = (chunk & 1) * 24;
    const float* xb = x   + (b * 1024 + c0) * 2304 + ty * 48 + tx;
    float*       ob = out + (b * 1024 + c0) * 2304 + ty * 48 + tx;

#pragma unroll
    for (int e = tid; e < 512; e += 256) {
        int c = e >> 4, slq = e & 15;
        int sl = slq * 4;
        int s = s0 + sl;
        int si = s / 24, sj = s - si * 24;
        int addr = c * 2304 + si * 48 + sj;
        float4 xv = *(const float4*)&xb[addr];
        float t0 = tile[(sl + 0) * 33 + c];
        float t1 = tile[(sl + 1) * 33 + c];
        float t2 = tile[(sl + 2) * 33 + c];
        float t3 = tile[(sl + 3) * 33 + c];
        float4 o;
        o.x = fmaxf(xv.x + t0, 0.f);
        o.y = fmaxf(xv.y + t1, 0.f);
        o.z = fmaxf(xv.z + t2, 0.f);
        o.w = fmaxf(xv.w + t3, 0.f);
        *(float4*)&ob[addr] = o;
    }
}

// ---------------- host launch ---------------------------------------------
extern "C" void kernel_launch(void* const* d_in, const int* in_sizes, int n_in,
                              void* d_out, int out_size)
{
    const float* x     = (const float*)d_in[0];
    const float* w1    = (const float*)d_in[1];
    const float* b1    = (const float*)d_in[2];
    const float* w2    = (const float*)d_in[3];
    const float* b2    = (const float*)d_in[4];
    const float* w3    = (const float*)d_in[5];
    const float* b3    = (const float*)d_in[6];
    const float* w4    = (const float*)d_in[7];
    const float* b4    = (const float*)d_in[8];
    const float* gamma = (const float*)d_in[9];
    const float* beta  = (const float*)d_in[10];
    float* out = (float*)d_out;

    const int K2AB_SMEM = (73 * 516 + 512 * 12 + 73 * 12 + 72 * 72 + 72 + 72 + 512) * 4;

    cudaFuncSetAttribute(k01_prep_gemm1, cudaFuncAttributeMaxDynamicSharedMemorySize,
                         96 * 132 * 4);
    cudaFuncSetAttribute(k2ab_moments, cudaFuncAttributeMaxDynamicSharedMemorySize,
                         K2AB_SMEM);
    cudaFuncSetAttribute(k5_out2, cudaFuncAttributeMaxDynamicSharedMemorySize,
                         H_DIM * 128 * 4);

    k01_prep_gemm1<<<74 + 512, 256, 96 * 132 * 4>>>(x, w1, b1, w2, b2, w3);
    k2ab_moments<<<128, 256, K2AB_SMEM>>>();
    k4_combine<<<256, 256>>>(b3);
    k5_out2<<<dim3(512, 9), 256, H_DIM * 128 * 4>>>(w4, b4);   // 4th -> ncu
    k6_reduce<<<S_DIM, 256>>>(gamma, beta);
    k7_final<<<dim3(9, 32, 64), 256>>>(x, out);
}

// round 17
// speedup vs baseline: 1.1889x; 1.0369x over previous
#include <cuda_runtime.h>
#include <math.h>

#define N_TOT 65536      // B(64) * C(1024) columns
#define S_DIM 576
#define H_DIM 72
#define NT 11            // Taylor terms t = 0..10 of exp(2 xm_c xm_d)

// ---------------- scratch (device globals; no allocation allowed) ----------
__device__ float g_H1[H_DIM * N_TOT];          // 18.9 MB
__device__ float g_H2[H_DIM * N_TOT];          // 18.9 MB
__device__ float g_xm[N_TOT];
__device__ float g_out2[S_DIM * N_TOT];        // 151 MB
__device__ float g_psum[S_DIM * 512];          // BN partials per (s, ntile)
__device__ float g_psq [S_DIM * 512];
__device__ float g_R[128 * 73 * 12];           // per-group R_t (row 72 = m_t)
__device__ float g_M[H_DIM * H_DIM];
__device__ float g_yb[H_DIM];
__device__ float g_w2m[H_DIM];
__device__ float g_b2m;
__device__ float g_scale[S_DIM];
__device__ float g_shift[S_DIM];

// ---------------- K01: prep (blocks 0..73) + gemm1 (74..585)  [verbatim] ---
__global__ void __launch_bounds__(256) k01_prep_gemm1(
    const float* __restrict__ x,  const float* __restrict__ W1,
    const float* __restrict__ b1, const float* __restrict__ W2,
    const float* __restrict__ b2, const float* __restrict__ W3)
{
    __shared__ float row[S_DIM];
    __shared__ __align__(16) float wt[96 * 100];   // [sl][og*12 + k], 38.4 KB
    extern __shared__ __align__(16) float xt[];    // [96][132] = 50.7 KB dyn

    if (blockIdx.x < 74) {
        int o = blockIdx.x;
        if (o < H_DIM) {
            for (int e = threadIdx.x; e < S_DIM; e += 256) row[e] = W3[o * S_DIM + e];
            __syncthreads();
            if (threadIdx.x < H_DIM) {
                int j = threadIdx.x;
                float a = 0.f;
                for (int s = 0; s < S_DIM; s++) a = fmaf(row[s], W2[s * H_DIM + j], a);
                g_M[o * H_DIM + j] = a;
            }
        } else if (o == H_DIM) {
            for (int e = threadIdx.x; e < S_DIM; e += 256) row[e] = b2[e];
            __syncthreads();
            if (threadIdx.x < H_DIM) {
                int oo = threadIdx.x;
                float a = 0.f;
                for (int s = 0; s < S_DIM; s++) a = fmaf(W3[oo * S_DIM + s], row[s], a);
                g_yb[oo] = a;
            }
        } else {
            if (threadIdx.x < H_DIM) {
                int j = threadIdx.x;
                float a = 0.f;
                for (int s = 0; s < S_DIM; s++) a += W2[s * H_DIM + j];
                g_w2m[j] = a * (1.f / (float)S_DIM);
            }
            if (threadIdx.x == H_DIM) {
                float a = 0.f;
                for (int s = 0; s < S_DIM; s++) a += b2[s];
                g_b2m = a * (1.f / (float)S_DIM);
            }
        }
        return;
    }

    int n0 = (blockIdx.x - 74) * 128;
    int B  = n0 >> 10;
    int c0 = n0 & 1023;
    int b = B & 15, chunk = B >> 4;
    int ty = (chunk >> 1) * 24, tx = (chunk & 1) * 24;
    int tid = threadIdx.x;
    int nl = tid & 31, og = tid >> 5;

    const float* xb = x + (b * 1024 + c0) * 2304 + ty * 48 + tx;

    float acc[9][4];
#pragma unroll
    for (int k = 0; k < 9; k++)
#pragma unroll
        for (int j = 0; j < 4; j++) acc[k][j] = 0.f;

    for (int t = 0; t < 6; t++) {
        for (int e = tid; e < 96 * 128; e += 256) {
            int cl = e / 96, sl = e - cl * 96;
            int s = t * 96 + sl;
            int si = s / 24, sj = s - si * 24;
            xt[sl * 132 + cl] = xb[cl * 2304 + si * 48 + sj];
        }
        for (int e = tid; e < 72 * 96; e += 256) {
            int o = e / 96, sl = e - o * 96;
            int oq = o / 9, ok = o - oq * 9;
            wt[sl * 100 + oq * 12 + ok] = W1[o * S_DIM + t * 96 + sl];
        }
        __syncthreads();
#pragma unroll 4
        for (int sl = 0; sl < 96; sl++) {
            float4 av = *(const float4*)&xt[sl * 132 + nl * 4];
            const float* wp = &wt[sl * 100 + og * 12];
            float4 w0 = *(const float4*)wp;
            float4 w1 = *(const float4*)(wp + 4);
            float  w8 = wp[8];
            acc[0][0] = fmaf(w0.x, av.x, acc[0][0]); acc[0][1] = fmaf(w0.x, av.y, acc[0][1]);
            acc[0][2] = fmaf(w0.x, av.z, acc[0][2]); acc[0][3] = fmaf(w0.x, av.w, acc[0][3]);
            acc[1][0] = fmaf(w0.y, av.x, acc[1][0]); acc[1][1] = fmaf(w0.y, av.y, acc[1][1]);
            acc[1][2] = fmaf(w0.y, av.z, acc[1][2]); acc[1][3] = fmaf(w0.y, av.w, acc[1][3]);
            acc[2][0] = fmaf(w0.z, av.x, acc[2][0]); acc[2][1] = fmaf(w0.z, av.y, acc[2][1]);
            acc[2][2] = fmaf(w0.z, av.z, acc[2][2]); acc[2][3] = fmaf(w0.z, av.w, acc[2][3]);
            acc[3][0] = fmaf(w0.w, av.x, acc[3][0]); acc[3][1] = fmaf(w0.w, av.y, acc[3][1]);
            acc[3][2] = fmaf(w0.w, av.z, acc[3][2]); acc[3][3] = fmaf(w0.w, av.w, acc[3][3]);
            acc[4][0] = fmaf(w1.x, av.x, acc[4][0]); acc[4][1] = fmaf(w1.x, av.y, acc[4][1]);
            acc[4][2] = fmaf(w1.x, av.z, acc[4][2]); acc[4][3] = fmaf(w1.x, av.w, acc[4][3]);
            acc[5][0] = fmaf(w1.y, av.x, acc[5][0]); acc[5][1] = fmaf(w1.y, av.y, acc[5][1]);
            acc[5][2] = fmaf(w1.y, av.z, acc[5][2]); acc[5][3] = fmaf(w1.y, av.w, acc[5][3]);
            acc[6][0] = fmaf(w1.z, av.x, acc[6][0]); acc[6][1] = fmaf(w1.z, av.y, acc[6][1]);
            acc[6][2] = fmaf(w1.z, av.z, acc[6][2]); acc[6][3] = fmaf(w1.z, av.w, acc[6][3]);
            acc[7][0] = fmaf(w1.w, av.x, acc[7][0]); acc[7][1] = fmaf(w1.w, av.y, acc[7][1]);
            acc[7][2] = fmaf(w1.w, av.z, acc[7][2]); acc[7][3] = fmaf(w1.w, av.w, acc[7][3]);
            acc[8][0] = fmaf(w8,   av.x, acc[8][0]); acc[8][1] = fmaf(w8,   av.y, acc[8][1]);
            acc[8][2] = fmaf(w8,   av.z, acc[8][2]); acc[8][3] = fmaf(w8,   av.w, acc[8][3]);
        }
        __syncthreads();
    }
#pragma unroll
    for (int k = 0; k < 9; k++) {
        int o = og * 9 + k;
        float bb = b1[o];
        float4 v;
        v.x = fmaxf(acc[k][0] + bb, 0.f);
        v.y = fmaxf(acc[k][1] + bb, 0.f);
        v.z = fmaxf(acc[k][2] + bb, 0.f);
        v.w = fmaxf(acc[k][3] + bb, 0.f);
        *(float4*)&g_H1[o * N_TOT + n0 + nl * 4] = v;
    }
}

// ---------------- K2ab: fused xm + per-group moments + R_t  [verbatim] -----
__global__ void __launch_bounds__(256) k2ab_moments(void)
{
    extern __shared__ __align__(16) float sm[];
    float* hs   = sm;                        // [73][516]  (row 72 = ones)
    float* qs   = hs + 73 * 516;             // [512][12]  (col 11 zeroed)
    float* ps   = qs + 512 * 12;             // [73][12]
    float* Ms   = ps + 73 * 12;              // [72][72]
    float* ybs  = Ms + 72 * 72;              // [72]
    float* w2ms = ybs + 72;                  // [72]
    float* xms  = w2ms + 72;                 // [512]

    int g = blockIdx.x;
    int nb = g * 512;
    int tid = threadIdx.x;

    for (int e = tid; e < 73 * 128; e += 256) {
        int j = e >> 7, c4 = e & 127;
        float4 v = (j < H_DIM)
            ? *(const float4*)&g_H1[j * N_TOT + nb + c4 * 4]
            : make_float4(1.f, 1.f, 1.f, 1.f);
        *(float4*)&hs[j * 516 + c4 * 4] = v;
    }
    for (int e = tid; e < H_DIM * H_DIM; e += 256) Ms[e] = g_M[e];
    if (tid < H_DIM) { ybs[tid] = g_yb[tid]; w2ms[tid] = g_w2m[tid]; }
    __syncthreads();

    for (int c = tid; c < 512; c += 256) {
        float xm = g_b2m;
#pragma unroll 8
        for (int p = 0; p < H_DIM; p++) xm = fmaf(w2ms[p], hs[p * 516 + c], xm);
        xms[c] = xm;
        g_xm[nb + c] = xm;
        float a = __expf(-xm * xm);
        float pw = a;
#pragma unroll
        for (int t = 0; t < NT; t++) { qs[c * 12 + t] = pw; pw *= xm; }
        qs[c * 12 + NT] = 0.f;
    }
    __syncthreads();

    if (tid < 219) {
        int j = tid / 3, tg = tid - 3 * (tid / 3);
        int t0 = tg * 4;
        float a0 = 0.f, a1 = 0.f, a2 = 0.f, a3 = 0.f;
        const float* hrow = &hs[j * 516];
        for (int c = 0; c < 512; c++) {
            float hv = hrow[c];
            float4 qv = *(const float4*)&qs[c * 12 + t0];
            a0 = fmaf(hv, qv.x, a0);
            a1 = fmaf(hv, qv.y, a1);
            a2 = fmaf(hv, qv.z, a2);
            a3 = fmaf(hv, qv.w, a3);
        }
        ps[j * 12 + t0 + 0] = a0;
        ps[j * 12 + t0 + 1] = a1;
        ps[j * 12 + t0 + 2] = a2;
        if (tg < 2) ps[j * 12 + t0 + 3] = a3;
        else        ps[j * 12 + 11]     = 0.f;
    }
    __syncthreads();

    if (tid < 216) {
        int j = tid / 3, tg = tid - 3 * (tid / 3);
        int t0 = tg * 4;
        float a0 = 0.f, a1 = 0.f, a2 = 0.f, a3 = 0.f;
        for (int p = 0; p < H_DIM; p++) {
            float mv = Ms[j * H_DIM + p];
            float4 pv = *(const float4*)&ps[p * 12 + t0];
            a0 = fmaf(mv, pv.x, a0);
            a1 = fmaf(mv, pv.y, a1);
            a2 = fmaf(mv, pv.z, a2);
            a3 = fmaf(mv, pv.w, a3);
        }
        float yv = ybs[j];
        float4 mm = *(const float4*)&ps[72 * 12 + t0];
        a0 = fmaf(yv, mm.x, a0);
        a1 = fmaf(yv, mm.y, a1);
        a2 = fmaf(yv, mm.z, a2);
        a3 = fmaf(yv, mm.w, a3);
        float* rp = &g_R[(g * 73 + j) * 12 + t0];
        rp[0] = a0; rp[1] = a1; rp[2] = a2;
        if (tg < 2) rp[3] = a3;
    } else if (tid < 219) {
        int tg = tid - 216;
        int t0 = tg * 4;
        int nt = (tg == 2) ? 3 : 4;
        for (int i = 0; i < nt; i++)
            g_R[(g * 73 + 72) * 12 + t0 + i] = ps[72 * 12 + t0 + i];
    }
}

// ---------------- K4c: H2[j,d] = relu(b3 + (sum_t w_t R_t[j]) / U_d) -------
__global__ void __launch_bounds__(256) k4_combine(const float* __restrict__ b3)
{
    __shared__ __align__(16) float Rs[73 * 12];
    __shared__ float b3s[H_DIM];
    int g = blockIdx.x >> 1;
    int d = blockIdx.x * 256 + threadIdx.x;
    int tid = threadIdx.x;

    for (int e = tid; e < 73 * 12; e += 256) Rs[e] = g_R[g * 73 * 12 + e];
    if (tid < H_DIM) b3s[tid] = b3[tid];
    __syncthreads();

    float xm = g_xm[d];
    float w[NT];
    w[0] = 1.f;
    w[1] = 2.f * xm;
    w[2] = w[1] * xm;
    w[3] = w[2] * xm * (2.f / 3.f);
    w[4] = w[3] * xm * 0.5f;
    w[5] = w[4] * xm * 0.4f;
    w[6] = w[5] * xm * (1.f / 3.f);
    w[7] = w[6] * xm * (2.f / 7.f);
    w[8] = w[7] * xm * 0.25f;
    w[9] = w[8] * xm * (2.f / 9.f);
    w[10] = w[9] * xm * 0.2f;

    float U = 0.f;
#pragma unroll
    for (int t = 0; t < NT; t++) U = fmaf(w[t], Rs[72 * 12 + t], U);
    float invU = 1.f / U;

#pragma unroll 8
    for (int j = 0; j < H_DIM; j++) {
        float s = 0.f;
#pragma unroll
        for (int t = 0; t < NT; t++) s = fmaf(w[t], Rs[j * 12 + t], s);
        g_H2[j * N_TOT + d] = fmaxf(fmaf(s, invU, b3s[j]), 0.f);
    }
}

// ---------------- K5 v2: out2 GEMM + BN partials, VECTORIZED weights -------
// ws transposed to [p][64]: per-thread 8 weights = 2 broadcast LDS.128.
// smem phases per p: 4 (ht) + 2 (ws) = 6  vs 16 FFMA-cyc -> FFMA-bound.
__global__ void __launch_bounds__(256) k5_out2(const float* __restrict__ W4,
                                               const float* __restrict__ b4)
{
    extern __shared__ float ht[];                  // [72][128] = 36864 B
    __shared__ __align__(16) float ws[72 * 64];    // [p][j], 18432 B
    __shared__ float b4s[64];
    int n0 = blockIdx.x * 128;
    int s0 = blockIdx.y * 64;
    int tid = threadIdx.x;
    int nl = tid & 31, sg = tid >> 5;

    for (int e = tid; e < H_DIM * 128; e += 256) {
        int p = e >> 7, cl = e & 127;
        ht[e] = g_H2[p * N_TOT + n0 + cl];
    }
    for (int e = tid; e < H_DIM * 64; e += 256) {
        int p = e >> 6, j = e & 63;
        ws[p * 64 + j] = W4[(s0 + j) * H_DIM + p];
    }
    if (tid < 64) b4s[tid] = b4[s0 + tid];
    __syncthreads();

    float acc[8][4];
#pragma unroll
    for (int k = 0; k < 8; k++)
#pragma unroll
        for (int j = 0; j < 4; j++) acc[k][j] = 0.f;

#pragma unroll 4
    for (int p = 0; p < H_DIM; p++) {
        float4 av = *(const float4*)&ht[p * 128 + nl * 4];
        const float* wp = &ws[p * 64 + sg * 8];
        float4 w0 = *(const float4*)wp;
        float4 w1 = *(const float4*)(wp + 4);
        acc[0][0] = fmaf(w0.x, av.x, acc[0][0]); acc[0][1] = fmaf(w0.x, av.y, acc[0][1]);
        acc[0][2] = fmaf(w0.x, av.z, acc[0][2]); acc[0][3] = fmaf(w0.x, av.w, acc[0][3]);
        acc[1][0] = fmaf(w0.y, av.x, acc[1][0]); acc[1][1] = fmaf(w0.y, av.y, acc[1][1]);
        acc[1][2] = fmaf(w0.y, av.z, acc[1][2]); acc[1][3] = fmaf(w0.y, av.w, acc[1][3]);
        acc[2][0] = fmaf(w0.z, av.x, acc[2][0]); acc[2][1] = fmaf(w0.z, av.y, acc[2][1]);
        acc[2][2] = fmaf(w0.z, av.z, acc[2][2]); acc[2][3] = fmaf(w0.z, av.w, acc[2][3]);
        acc[3][0] = fmaf(w0.w, av.x, acc[3][0]); acc[3][1] = fmaf(w0.w, av.y, acc[3][1]);
        acc[3][2] = fmaf(w0.w, av.z, acc[3][2]); acc[3][3] = fmaf(w0.w, av.w, acc[3][3]);
        acc[4][0] = fmaf(w1.x, av.x, acc[4][0]); acc[4][1] = fmaf(w1.x, av.y, acc[4][1]);
        acc[4][2] = fmaf(w1.x, av.z, acc[4][2]); acc[4][3] = fmaf(w1.x, av.w, acc[4][3]);
        acc[5][0] = fmaf(w1.y, av.x, acc[5][0]); acc[5][1] = fmaf(w1.y, av.y, acc[5][1]);
        acc[5][2] = fmaf(w1.y, av.z, acc[5][2]); acc[5][3] = fmaf(w1.y, av.w, acc[5][3]);
        acc[6][0] = fmaf(w1.z, av.x, acc[6][0]); acc[6][1] = fmaf(w1.z, av.y, acc[6][1]);
        acc[6][2] = fmaf(w1.z, av.z, acc[6][2]); acc[6][3] = fmaf(w1.z, av.w, acc[6][3]);
        acc[7][0] = fmaf(w1.w, av.x, acc[7][0]); acc[7][1] = fmaf(w1.w, av.y, acc[7][1]);
        acc[7][2] = fmaf(w1.w, av.z, acc[7][2]); acc[7][3] = fmaf(w1.w, av.w, acc[7][3]);
    }
#pragma unroll
    for (int k = 0; k < 8; k++) {
        int s = s0 + sg * 8 + k;
        float bb = b4s[sg * 8 + k];
        float4 v;
        v.x = acc[k][0] + bb; v.y = acc[k][1] + bb;
        v.z = acc[k][2] + bb; v.w = acc[k][3] + bb;
        *(float4*)&g_out2[s * N_TOT + n0 + nl * 4] = v;

        float sm = (v.x + v.y) + (v.z + v.w);
        float sq = (v.x * v.x + v.y * v.y) + (v.z * v.z + v.w * v.w);
#pragma unroll
        for (int off = 16; off; off >>= 1) {
            sm += __shfl_down_sync(0xffffffffu, sm, off);
            sq += __shfl_down_sync(0xffffffffu, sq, off);
        }
        if (nl == 0) {
            g_psum[s * 512 + blockIdx.x] = sm;
            g_psq [s * 512 + blockIdx.x] = sq;
        }
    }
}

// ---------------- K6r: reduce BN partials -> scale/shift  [verbatim] -------
__global__ void __launch_bounds__(256) k6_reduce(const float* __restrict__ gamma,
                                                 const float* __restrict__ beta)
{
    __shared__ float s1[8], s2[8];
    int s = blockIdx.x;
    int tid = threadIdx.x;
    float a = 0.f, q = 0.f;
    for (int i = tid; i < 512; i += 256) {
        a += g_psum[s * 512 + i];
        q += g_psq [s * 512 + i];
    }
#pragma unroll
    for (int off = 16; off; off >>= 1) {
        a += __shfl_down_sync(0xffffffffu, a, off);
        q += __shfl_down_sync(0xffffffffu, q, off);
    }
    int w = tid >> 5, l = tid & 31;
    if (l == 0) { s1[w] = a; s2[w] = q; }
    __syncthreads();
    if (tid == 0) {
        float aa = 0.f, qq = 0.f;
        for (int i = 0; i < 8; i++) { aa += s1[i]; qq += s2[i]; }
        float mu = aa * (1.f / (float)N_TOT);
        float var = qq * (1.f / (float)N_TOT) - mu * mu;
        float rstd = rsqrtf(var + 1e-5f);
        float ga = gamma[s];
        g_scale[s] = rstd * ga * 0.25f;
        g_shift[s] = (beta[s] - mu * rstd * ga) * 0.25f;
    }
}

// ---------------- K7 v2: vectorized normalize + scatter  [verbatim] --------
__global__ void __launch_bounds__(256) k7_final(
    const float* __restrict__ x, float* __restrict__ out)
{
    __shared__ float tile[64 * 33];
    __shared__ float scs[64], shs[64];
    int s0 = blockIdx.x * 64;
    int c0 = blockIdx.y * 32;
    int B  = blockIdx.z;
    int n0 = B * 1024 + c0;
    int tid = threadIdx.x;

    if (tid < 64) { scs[tid] = g_scale[s0 + tid]; shs[tid] = g_shift[s0 + tid]; }
    __syncthreads();

#pragma unroll
    for (int e = tid; e < 512; e += 256) {
        int sl = e >> 3, cl4 = e & 7;
        float4 v = *(const float4*)&g_out2[(s0 + sl) * N_TOT + n0 + cl4 * 4];
        float sc = scs[sl], sh = shs[sl];
        float* tp = &tile[sl * 33 + cl4 * 4];
        tp[0] = fmaf(v.x, sc, sh);
        tp[1] = fmaf(v.y, sc, sh);
        tp[2] = fmaf(v.z, sc, sh);
        tp[3] = fmaf(v.w, sc, sh);
    }
    __syncthreads();

    int b = B & 15, chunk = B >> 4;
    int ty = (chunk >> 1) * 24, tx = (chunk & 1) * 24;
    const float* xb = x   + (b * 1024 + c0) * 2304 + ty * 48 + tx;
    float*       ob = out + (b * 1024 + c0) * 2304 + ty * 48 + tx;

#pragma unroll
    for (int e = tid; e < 512; e += 256) {
        int c = e >> 4, slq = e & 15;
        int sl = slq * 4;
        int s = s0 + sl;
        int si = s / 24, sj = s - si * 24;
        int addr = c * 2304 + si * 48 + sj;
        float4 xv = *(const float4*)&xb[addr];
        float t0 = tile[(sl + 0) * 33 + c];
        float t1 = tile[(sl + 1) * 33 + c];
        float t2 = tile[(sl + 2) * 33 + c];
        float t3 = tile[(sl + 3) * 33 + c];
        float4 o;
        o.x = fmaxf(xv.x + t0, 0.f);
        o.y = fmaxf(xv.y + t1, 0.f);
        o.z = fmaxf(xv.z + t2, 0.f);
        o.w = fmaxf(xv.w + t3, 0.f);
        *(float4*)&ob[addr] = o;
    }
}

// ---------------- host launch ---------------------------------------------
extern "C" void kernel_launch(void* const* d_in, const int* in_sizes, int n_in,
                              void* d_out, int out_size)
{
    const float* x     = (const float*)d_in[0];
    const float* w1    = (const float*)d_in[1];
    const float* b1    = (const float*)d_in[2];
    const float* w2    = (const float*)d_in[3];
    const float* b2    = (const float*)d_in[4];
    const float* w3    = (const float*)d_in[5];
    const float* b3    = (const float*)d_in[6];
    const float* w4    = (const float*)d_in[7];
    const float* b4    = (const float*)d_in[8];
    const float* gamma = (const float*)d_in[9];
    const float* beta  = (const float*)d_in[10];
    float* out = (float*)d_out;

    const int K2AB_SMEM = (73 * 516 + 512 * 12 + 73 * 12 + 72 * 72 + 72 + 72 + 512) * 4;

    cudaFuncSetAttribute(k01_prep_gemm1, cudaFuncAttributeMaxDynamicSharedMemorySize,
                         96 * 132 * 4);
    cudaFuncSetAttribute(k2ab_moments, cudaFuncAttributeMaxDynamicSharedMemorySize,
                         K2AB_SMEM);
    cudaFuncSetAttribute(k5_out2, cudaFuncAttributeMaxDynamicSharedMemorySize,
                         H_DIM * 128 * 4);

    k01_prep_gemm1<<<74 + 512, 256, 96 * 132 * 4>>>(x, w1, b1, w2, b2, w3);
    k2ab_moments<<<128, 256, K2AB_SMEM>>>();
    k4_combine<<<256, 256>>>(b3);
    k5_out2<<<dim3(512, 9), 256, H_DIM * 128 * 4>>>(w4, b4);   // 4th -> ncu
    k6_reduce<<<S_DIM, 256>>>(gamma, beta);
    k7_final<<<dim3(9, 32, 64), 256>>>(x, out);
}